// round 15
// baseline (speedup 1.0000x reference)
#include <cuda_runtime.h>
#include <cuda_bf16.h>
#include <mma.h>
#include <cstdint>

using namespace nvcuda;

#define MTOK  8192
#define D_    768
#define NCODE 16384
#define THRv  100.0f

#define BM 128
#define BN 128
#define BK 32
#define NSPLIT 16
#define NCHUNK (NCODE / NSPLIT)       // 1024
#define NTILES (NCHUNK / BN)          // 8
#define NKSTEP (D_ / BK)              // 24
#define SROW   40                     // padded bf16 smem row (elems); 80B pitch
#define NCAND  (NSPLIT * 2)           // 32 slots: one per (split, column-half)

// Scratch (static device memory — allocations are forbidden).
// Referenced ONLY from device code by symbol.
__device__ float g_c2[NCODE];
__device__ float g_x2[MTOK];
__device__ unsigned long long g_cand[MTOK * NCAND];
__device__ __align__(16) __nv_bfloat16 g_xb[MTOK * D_];
__device__ __align__(16) __nv_bfloat16 g_cb[NCODE * D_];

// ---------------------------------------------------------------------------
// Fused convert + row-norm kernels: one block (96 threads) per row.
// Each thread converts 8 fp32 -> 8 bf16 (one uint4) and accumulates v^2.
__device__ __forceinline__ uint4 cvt8(float4 u, float4 v) {
    __nv_bfloat162 p0 = __floats2bfloat162_rn(u.x, u.y);
    __nv_bfloat162 p1 = __floats2bfloat162_rn(u.z, u.w);
    __nv_bfloat162 p2 = __floats2bfloat162_rn(v.x, v.y);
    __nv_bfloat162 p3 = __floats2bfloat162_rn(v.z, v.w);
    uint4 r;
    r.x = *(unsigned*)&p0; r.y = *(unsigned*)&p1;
    r.z = *(unsigned*)&p2; r.w = *(unsigned*)&p3;
    return r;
}

__device__ __forceinline__ float blockreduce96(float s) {
    __shared__ float part[3];
#pragma unroll
    for (int off = 16; off; off >>= 1) s += __shfl_xor_sync(0xffffffffu, s, off);
    if ((threadIdx.x & 31) == 0) part[threadIdx.x >> 5] = s;
    __syncthreads();
    return part[0] + part[1] + part[2];
}

__global__ __launch_bounds__(96) void cvt_x_kernel(const float* __restrict__ in) {
    const int row = blockIdx.x;
    const int tid = threadIdx.x;
    const float4* p = (const float4*)(in + (size_t)row * D_) + 2 * tid;
    float4 u = p[0], v = p[1];
    ((uint4*)(g_xb + (size_t)row * D_))[tid] = cvt8(u, v);
    float s = u.x * u.x + u.y * u.y + u.z * u.z + u.w * u.w
            + v.x * v.x + v.y * v.y + v.z * v.z + v.w * v.w;
    s = blockreduce96(s);
    if (tid == 0) g_x2[row] = s;
}

__global__ __launch_bounds__(96) void cvt_c_kernel(const float* __restrict__ in,
                                                   const unsigned char* __restrict__ act8) {
    const int row = blockIdx.x;
    const int tid = threadIdx.x;
    const float4* p = (const float4*)(in + (size_t)row * D_) + 2 * tid;
    float4 u = p[0], v = p[1];
    ((uint4*)(g_cb + (size_t)row * D_))[tid] = cvt8(u, v);
    float s = u.x * u.x + u.y * u.y + u.z * u.z + u.w * u.w
            + v.x * v.x + v.y * v.y + v.z * v.z + v.w * v.w;
    s = blockreduce96(s);
    if (tid == 0) {
        bool int32mode = (act8[0] == 1) && (act8[1] == 0) && (act8[2] == 0) && (act8[3] == 0);
        bool a = int32mode ? (((const int*)act8)[row] != 0) : (act8[row] != 0);
        g_c2[row] = a ? s : __int_as_float(0x7f800000);
    }
}

// ---------------------------------------------------------------------------
__device__ __forceinline__ unsigned float_to_ordered(float f) {
    unsigned b = __float_as_uint(f);
    return (b & 0x80000000u) ? ~b : (b | 0x80000000u);
}

// ---------------------------------------------------------------------------
// Selection GEMM: bf16 WMMA, 4 warps of 64x64 (2x2), staged-bf16 LDG,
// register double-buffered single-stage smem, 3 CTAs/SM. Per-(split,
// col-half) winner per token; disjoint plain stores (race-free).
// ---------------------------------------------------------------------------
__global__ __launch_bounds__(128, 3) void gemm_bf16_kernel() {
    __shared__ __align__(16) __nv_bfloat16 sA[BM * SROW];
    __shared__ __align__(16) __nv_bfloat16 sB[BN * SROW];
    __shared__ __align__(16) float sbuf[4][16 * 16];

    const int tid  = threadIdx.x;
    const int lane = tid & 31;
    const int warp = tid >> 5;      // 0..3
    const int wm = warp & 1;        // 0..1 -> 64 rows each
    const int wn = warp >> 1;       // 0..1 -> 64 cols each
    const int mBase  = blockIdx.x * BM;
    const int nChunk = blockIdx.y * NCHUNK;

    const int lrow = tid >> 2;           // 0..31 (rows +0,+32,+64,+96)
    const int lseg = (tid & 3) * 8;      // elem offset 0,8,16,24

    const __nv_bfloat16* Abase = g_xb + (size_t)(mBase + lrow) * D_ + lseg;

    // running per-row winners for this (split, col-half)
    float bestv[4];
    int   besti[4];
#pragma unroll
    for (int q = 0; q < 4; q++) { bestv[q] = __int_as_float(0x7f800000); besti[q] = nChunk; }

    for (int nt = 0; nt < NTILES; nt++) {
        const int nBase = nChunk + nt * BN;
        const __nv_bfloat16* Bbase = g_cb + (size_t)(nBase + lrow) * D_ + lseg;

        wmma::fragment<wmma::accumulator, 16, 16, 16, float> acc[4][4];
#pragma unroll
        for (int mi = 0; mi < 4; mi++)
#pragma unroll
            for (int ni = 0; ni < 4; ni++) wmma::fill_fragment(acc[mi][ni], 0.0f);

        // prologue: k-step 0 into registers
        uint4 rA[4], rB[4];
#pragma unroll
        for (int r = 0; r < 4; r++) {
            rA[r] = *(const uint4*)(Abase + (size_t)(r * 32) * D_);
            rB[r] = *(const uint4*)(Bbase + (size_t)(r * 32) * D_);
        }

        for (int kb = 0; kb < NKSTEP; kb++) {
            __syncthreads();   // previous k-step's MMAs done reading smem
#pragma unroll
            for (int r = 0; r < 4; r++) {
                *(uint4*)&sA[(lrow + r * 32) * SROW + lseg] = rA[r];
                *(uint4*)&sB[(lrow + r * 32) * SROW + lseg] = rB[r];
            }
            __syncthreads();
            if (kb + 1 < NKSTEP) {
                const int kg = (kb + 1) * BK;
#pragma unroll
                for (int r = 0; r < 4; r++) {
                    rA[r] = *(const uint4*)(Abase + (size_t)(r * 32) * D_ + kg);
                    rB[r] = *(const uint4*)(Bbase + (size_t)(r * 32) * D_ + kg);
                }
            }
#pragma unroll
            for (int ks = 0; ks < 2; ks++) {
                wmma::fragment<wmma::matrix_a, 16, 16, 16, __nv_bfloat16, wmma::row_major> fa[4];
#pragma unroll
                for (int mi = 0; mi < 4; mi++)
                    wmma::load_matrix_sync(fa[mi], &sA[(wm * 64 + mi * 16) * SROW + ks * 16], SROW);
#pragma unroll
                for (int ni = 0; ni < 4; ni++) {
                    // smem B is [n][k]; as a KxN matrix that's col_major with ldm=SROW
                    wmma::fragment<wmma::matrix_b, 16, 16, 16, __nv_bfloat16, wmma::col_major> fb;
                    wmma::load_matrix_sync(fb, &sB[(wn * 64 + ni * 16) * SROW + ks * 16], SROW);
#pragma unroll
                    for (int mi = 0; mi < 4; mi++)
                        wmma::mma_sync(acc[mi][ni], fa[mi], fb, acc[mi][ni]);
                }
            }
        }

        // drain frags through smem (explicit indices), update running mins
#pragma unroll
        for (int mi = 0; mi < 4; mi++) {
#pragma unroll
            for (int ni = 0; ni < 4; ni++) {
                wmma::store_matrix_sync(&sbuf[warp][0], acc[mi][ni], 16, wmma::mem_row_major);
                __syncwarp();
                const int lr = lane >> 1;
                const int cb = (lane & 1) * 8;
                const int gcol0 = nBase + wn * 64 + ni * 16 + cb;
#pragma unroll
                for (int c = 0; c < 8; c++) {
                    float dot = sbuf[warp][lr * 16 + cb + c];
                    float s = fmaf(-2.0f, dot, g_c2[gcol0 + c]);
                    if (s < bestv[mi]) { bestv[mi] = s; besti[mi] = gcol0 + c; }
                }
                __syncwarp();
            }
        }
    }

    // merge lane pairs and store this (split, half)'s winner — disjoint slots.
    const int slot = blockIdx.y * 2 + wn;
#pragma unroll
    for (int mi = 0; mi < 4; mi++) {
        unsigned long long key =
            (((unsigned long long)float_to_ordered(bestv[mi])) << 32) | (unsigned)besti[mi];
        unsigned long long o = __shfl_xor_sync(0xffffffffu, key, 1);
        if (o < key) key = o;
        if ((lane & 1) == 0) {
            int row = mBase + wm * 64 + mi * 16 + (lane >> 1);
            g_cand[(size_t)row * NCAND + slot] = key;
        }
    }
}

// ---------------------------------------------------------------------------
// Exact fp32 rescoring of the 32 nominees per token; emits final outputs.
// ---------------------------------------------------------------------------
__global__ __launch_bounds__(256) void refine_kernel(const float* __restrict__ x,
                                                     const float* __restrict__ codes,
                                                     float* __restrict__ out, int out_size) {
    const int t = blockIdx.x * 8 + (threadIdx.x >> 5);
    const int lane = threadIdx.x & 31;
    if (t >= MTOK) return;

    const float4* xr = (const float4*)(x + (size_t)t * D_);
    float4 xv[6];
#pragma unroll
    for (int j = 0; j < 6; j++) xv[j] = xr[lane + j * 32];

    unsigned long long best = 0xFFFFFFFFFFFFFFFFULL;

    for (int c = 0; c < NCAND; c++) {
        unsigned idx = (unsigned)(g_cand[(size_t)t * NCAND + c] & 0xffffffffu);
        if (idx >= NCODE) continue;             // safety guard
        const float4* cr = (const float4*)(codes + (size_t)idx * D_);
        float s = 0.f;
#pragma unroll
        for (int j = 0; j < 6; j++) {
            float4 cv = cr[lane + j * 32];
            s += xv[j].x * cv.x + xv[j].y * cv.y + xv[j].z * cv.z + xv[j].w * cv.w;
        }
#pragma unroll
        for (int off = 16; off; off >>= 1) s += __shfl_xor_sync(0xffffffffu, s, off);
        float dist = fmaf(-2.0f, s, g_c2[idx]);   // exact fp32 score; inf if inactive
        unsigned long long key =
            (((unsigned long long)float_to_ordered(dist)) << 32) | (unsigned long long)idx;
        if (key < best) best = key;
    }

    if (lane == 0) {
        unsigned u = (unsigned)(best >> 32);
        unsigned b = (u & 0x80000000u) ? (u & 0x7fffffffu) : ~u;
        float s = __uint_as_float(b);
        int idx = (int)(best & 0xffffffffu);
        float dmin = g_x2[t] + s;
        int idx_out = (dmin <= THRv) ? idx : -1;
        if (best == 0xFFFFFFFFFFFFFFFFULL) { idx_out = -1; dmin = __int_as_float(0x7f800000); }
        out[t] = (float)idx_out;
        if (out_size >= 2 * MTOK) out[MTOK + t] = dmin;
    }
}

// ---------------------------------------------------------------------------
extern "C" void kernel_launch(void* const* d_in, const int* in_sizes, int n_in,
                              void* d_out, int out_size) {
    const float* x     = (const float*)d_in[0];
    const float* codes = (const float*)d_in[1];
    const unsigned char* act = (const unsigned char*)d_in[2];

    cvt_x_kernel<<<MTOK, 96>>>(x);
    cvt_c_kernel<<<NCODE, 96>>>(codes, act);
    gemm_bf16_kernel<<<dim3(MTOK / BM, NSPLIT), 128>>>();
    refine_kernel<<<MTOK / 8, 256>>>(x, codes, (float*)d_out, out_size);
}

// round 16
// speedup vs baseline: 3.5184x; 3.5184x over previous
#include <cuda_runtime.h>
#include <cuda_bf16.h>
#include <mma.h>
#include <cstdint>

using namespace nvcuda;

#define MTOK  8192
#define D_    768
#define NCODE 16384
#define THRv  100.0f

#define BM 128
#define BN 128
#define BK 32
#define NSPLIT 16
#define NCHUNK (NCODE / NSPLIT)       // 1024
#define NTILES (NCHUNK / BN)          // 8
#define NKSTEP (D_ / BK)              // 24
#define SROW   40                     // padded bf16 smem row (elems); 80B pitch
#define NCAND  (NSPLIT * 2)           // 32 slots: one per (split, column-half)

// Scratch (static device memory — allocations are forbidden).
// Referenced ONLY from device code by symbol.
__device__ float g_c2[NCODE];
__device__ float g_x2[MTOK];
__device__ unsigned long long g_cand[MTOK * NCAND];
__device__ __align__(16) __nv_bfloat16 g_xb[MTOK * D_];
__device__ __align__(16) __nv_bfloat16 g_cb[NCODE * D_];

// ---------------------------------------------------------------------------
// Fused convert + row-norm kernels: one block (96 threads) per row.
__device__ __forceinline__ uint4 cvt8(float4 u, float4 v) {
    __nv_bfloat162 p0 = __floats2bfloat162_rn(u.x, u.y);
    __nv_bfloat162 p1 = __floats2bfloat162_rn(u.z, u.w);
    __nv_bfloat162 p2 = __floats2bfloat162_rn(v.x, v.y);
    __nv_bfloat162 p3 = __floats2bfloat162_rn(v.z, v.w);
    uint4 r;
    r.x = *(unsigned*)&p0; r.y = *(unsigned*)&p1;
    r.z = *(unsigned*)&p2; r.w = *(unsigned*)&p3;
    return r;
}

__device__ __forceinline__ float blockreduce96(float s) {
    __shared__ float part[3];
#pragma unroll
    for (int off = 16; off; off >>= 1) s += __shfl_xor_sync(0xffffffffu, s, off);
    if ((threadIdx.x & 31) == 0) part[threadIdx.x >> 5] = s;
    __syncthreads();
    return part[0] + part[1] + part[2];
}

__global__ __launch_bounds__(96) void cvt_x_kernel(const float* __restrict__ in) {
    const int row = blockIdx.x;
    const int tid = threadIdx.x;
    const float4* p = (const float4*)(in + (size_t)row * D_) + 2 * tid;
    float4 u = p[0], v = p[1];
    ((uint4*)(g_xb + (size_t)row * D_))[tid] = cvt8(u, v);
    float s = u.x * u.x + u.y * u.y + u.z * u.z + u.w * u.w
            + v.x * v.x + v.y * v.y + v.z * v.z + v.w * v.w;
    s = blockreduce96(s);
    if (tid == 0) g_x2[row] = s;
}

__global__ __launch_bounds__(96) void cvt_c_kernel(const float* __restrict__ in,
                                                   const unsigned char* __restrict__ act8) {
    const int row = blockIdx.x;
    const int tid = threadIdx.x;
    const float4* p = (const float4*)(in + (size_t)row * D_) + 2 * tid;
    float4 u = p[0], v = p[1];
    ((uint4*)(g_cb + (size_t)row * D_))[tid] = cvt8(u, v);
    float s = u.x * u.x + u.y * u.y + u.z * u.z + u.w * u.w
            + v.x * v.x + v.y * v.y + v.z * v.z + v.w * v.w;
    s = blockreduce96(s);
    if (tid == 0) {
        bool int32mode = (act8[0] == 1) && (act8[1] == 0) && (act8[2] == 0) && (act8[3] == 0);
        bool a = int32mode ? (((const int*)act8)[row] != 0) : (act8[row] != 0);
        g_c2[row] = a ? s : __int_as_float(0x7f800000);
    }
}

// ---------------------------------------------------------------------------
__device__ __forceinline__ unsigned float_to_ordered(float f) {
    unsigned b = __float_as_uint(f);
    return (b & 0x80000000u) ? ~b : (b | 0x80000000u);
}

// ---------------------------------------------------------------------------
// Selection GEMM (R13 winner, verbatim): bf16 WMMA, 4 warps of 64x64 (2x2),
// staged-bf16 LDG, register double-buffered single-stage smem, 2 CTAs/SM
// (register-resident; 3 CTAs forces spills — measured 3x regression).
// ---------------------------------------------------------------------------
__global__ __launch_bounds__(128, 2) void gemm_bf16_kernel() {
    __shared__ __align__(16) __nv_bfloat16 sA[BM * SROW];
    __shared__ __align__(16) __nv_bfloat16 sB[BN * SROW];
    __shared__ __align__(16) float sbuf[4][16 * 16];

    const int tid  = threadIdx.x;
    const int lane = tid & 31;
    const int warp = tid >> 5;      // 0..3
    const int wm = warp & 1;        // 0..1 -> 64 rows each
    const int wn = warp >> 1;       // 0..1 -> 64 cols each
    const int mBase  = blockIdx.x * BM;
    const int nChunk = blockIdx.y * NCHUNK;

    const int lrow = tid >> 2;           // 0..31 (rows +0,+32,+64,+96)
    const int lseg = (tid & 3) * 8;      // elem offset 0,8,16,24

    const __nv_bfloat16* Abase = g_xb + (size_t)(mBase + lrow) * D_ + lseg;

    float bestv[4];
    int   besti[4];
#pragma unroll
    for (int q = 0; q < 4; q++) { bestv[q] = __int_as_float(0x7f800000); besti[q] = nChunk; }

    for (int nt = 0; nt < NTILES; nt++) {
        const int nBase = nChunk + nt * BN;
        const __nv_bfloat16* Bbase = g_cb + (size_t)(nBase + lrow) * D_ + lseg;

        wmma::fragment<wmma::accumulator, 16, 16, 16, float> acc[4][4];
#pragma unroll
        for (int mi = 0; mi < 4; mi++)
#pragma unroll
            for (int ni = 0; ni < 4; ni++) wmma::fill_fragment(acc[mi][ni], 0.0f);

        // prologue: k-step 0 into registers
        uint4 rA[4], rB[4];
#pragma unroll
        for (int r = 0; r < 4; r++) {
            rA[r] = *(const uint4*)(Abase + (size_t)(r * 32) * D_);
            rB[r] = *(const uint4*)(Bbase + (size_t)(r * 32) * D_);
        }

        for (int kb = 0; kb < NKSTEP; kb++) {
            __syncthreads();   // previous k-step's MMAs done reading smem
#pragma unroll
            for (int r = 0; r < 4; r++) {
                *(uint4*)&sA[(lrow + r * 32) * SROW + lseg] = rA[r];
                *(uint4*)&sB[(lrow + r * 32) * SROW + lseg] = rB[r];
            }
            __syncthreads();
            if (kb + 1 < NKSTEP) {
                const int kg = (kb + 1) * BK;
#pragma unroll
                for (int r = 0; r < 4; r++) {
                    rA[r] = *(const uint4*)(Abase + (size_t)(r * 32) * D_ + kg);
                    rB[r] = *(const uint4*)(Bbase + (size_t)(r * 32) * D_ + kg);
                }
            }
#pragma unroll
            for (int ks = 0; ks < 2; ks++) {
                wmma::fragment<wmma::matrix_a, 16, 16, 16, __nv_bfloat16, wmma::row_major> fa[4];
#pragma unroll
                for (int mi = 0; mi < 4; mi++)
                    wmma::load_matrix_sync(fa[mi], &sA[(wm * 64 + mi * 16) * SROW + ks * 16], SROW);
#pragma unroll
                for (int ni = 0; ni < 4; ni++) {
                    // smem B is [n][k]; as a KxN matrix that's col_major with ldm=SROW
                    wmma::fragment<wmma::matrix_b, 16, 16, 16, __nv_bfloat16, wmma::col_major> fb;
                    wmma::load_matrix_sync(fb, &sB[(wn * 64 + ni * 16) * SROW + ks * 16], SROW);
#pragma unroll
                    for (int mi = 0; mi < 4; mi++)
                        wmma::mma_sync(acc[mi][ni], fa[mi], fb, acc[mi][ni]);
                }
            }
        }

        // drain frags through smem (explicit indices), update running mins
#pragma unroll
        for (int mi = 0; mi < 4; mi++) {
#pragma unroll
            for (int ni = 0; ni < 4; ni++) {
                wmma::store_matrix_sync(&sbuf[warp][0], acc[mi][ni], 16, wmma::mem_row_major);
                __syncwarp();
                const int lr = lane >> 1;
                const int cb = (lane & 1) * 8;
                const int gcol0 = nBase + wn * 64 + ni * 16 + cb;
#pragma unroll
                for (int c = 0; c < 8; c++) {
                    float dot = sbuf[warp][lr * 16 + cb + c];
                    float s = fmaf(-2.0f, dot, g_c2[gcol0 + c]);
                    if (s < bestv[mi]) { bestv[mi] = s; besti[mi] = gcol0 + c; }
                }
                __syncwarp();
            }
        }
    }

    // merge lane pairs and store this (split, half)'s winner — disjoint slots.
    const int slot = blockIdx.y * 2 + wn;
#pragma unroll
    for (int mi = 0; mi < 4; mi++) {
        unsigned long long key =
            (((unsigned long long)float_to_ordered(bestv[mi])) << 32) | (unsigned)besti[mi];
        unsigned long long o = __shfl_xor_sync(0xffffffffu, key, 1);
        if (o < key) key = o;
        if ((lane & 1) == 0) {
            int row = mBase + wm * 64 + mi * 16 + (lane >> 1);
            g_cand[(size_t)row * NCAND + slot] = key;
        }
    }
}

// ---------------------------------------------------------------------------
// Exact fp32 rescoring of the 32 nominees per token; emits final outputs.
// ---------------------------------------------------------------------------
__global__ __launch_bounds__(256) void refine_kernel(const float* __restrict__ x,
                                                     const float* __restrict__ codes,
                                                     float* __restrict__ out, int out_size) {
    const int t = blockIdx.x * 8 + (threadIdx.x >> 5);
    const int lane = threadIdx.x & 31;
    if (t >= MTOK) return;

    const float4* xr = (const float4*)(x + (size_t)t * D_);
    float4 xv[6];
#pragma unroll
    for (int j = 0; j < 6; j++) xv[j] = xr[lane + j * 32];

    unsigned long long best = 0xFFFFFFFFFFFFFFFFULL;

    for (int c = 0; c < NCAND; c++) {
        unsigned idx = (unsigned)(g_cand[(size_t)t * NCAND + c] & 0xffffffffu);
        if (idx >= NCODE) continue;             // safety guard
        const float4* cr = (const float4*)(codes + (size_t)idx * D_);
        float s = 0.f;
#pragma unroll
        for (int j = 0; j < 6; j++) {
            float4 cv = cr[lane + j * 32];
            s += xv[j].x * cv.x + xv[j].y * cv.y + xv[j].z * cv.z + xv[j].w * cv.w;
        }
#pragma unroll
        for (int off = 16; off; off >>= 1) s += __shfl_xor_sync(0xffffffffu, s, off);
        float dist = fmaf(-2.0f, s, g_c2[idx]);   // exact fp32 score; inf if inactive
        unsigned long long key =
            (((unsigned long long)float_to_ordered(dist)) << 32) | (unsigned long long)idx;
        if (key < best) best = key;
    }

    if (lane == 0) {
        unsigned u = (unsigned)(best >> 32);
        unsigned b = (u & 0x80000000u) ? (u & 0x7fffffffu) : ~u;
        float s = __uint_as_float(b);
        int idx = (int)(best & 0xffffffffu);
        float dmin = g_x2[t] + s;
        int idx_out = (dmin <= THRv) ? idx : -1;
        if (best == 0xFFFFFFFFFFFFFFFFULL) { idx_out = -1; dmin = __int_as_float(0x7f800000); }
        out[t] = (float)idx_out;
        if (out_size >= 2 * MTOK) out[MTOK + t] = dmin;
    }
}

// ---------------------------------------------------------------------------
extern "C" void kernel_launch(void* const* d_in, const int* in_sizes, int n_in,
                              void* d_out, int out_size) {
    const float* x     = (const float*)d_in[0];
    const float* codes = (const float*)d_in[1];
    const unsigned char* act = (const unsigned char*)d_in[2];

    cvt_x_kernel<<<MTOK, 96>>>(x);
    cvt_c_kernel<<<NCODE, 96>>>(codes, act);
    gemm_bf16_kernel<<<dim3(MTOK / BM, NSPLIT), 128>>>();
    refine_kernel<<<MTOK / 8, 256>>>(x, codes, (float*)d_out, out_size);
}

// round 17
// speedup vs baseline: 3.7826x; 1.0751x over previous
#include <cuda_runtime.h>
#include <cuda_bf16.h>
#include <mma.h>
#include <cstdint>

using namespace nvcuda;

#define MTOK  8192
#define D_    768
#define NCODE 16384
#define THRv  100.0f

#define BM 128
#define BN 128
#define BK 64
#define NSPLIT 16
#define NCHUNK (NCODE / NSPLIT)       // 1024
#define NTILES (NCHUNK / BN)          // 8
#define NKSTEP (D_ / BK)              // 12
#define SROW   72                     // padded bf16 smem row (elems); 144B pitch
#define NCAND  (NSPLIT * 2)           // 32 slots: one per (split, column-half)

// Scratch (static device memory — allocations are forbidden).
// Referenced ONLY from device code by symbol.
__device__ float g_c2[NCODE];
__device__ float g_x2[MTOK];
__device__ unsigned long long g_cand[MTOK * NCAND];
__device__ __align__(16) __nv_bfloat16 g_xb[MTOK * D_];
__device__ __align__(16) __nv_bfloat16 g_cb[NCODE * D_];

// ---------------------------------------------------------------------------
// Fused convert + row-norm kernels: one block (96 threads) per row.
__device__ __forceinline__ uint4 cvt8(float4 u, float4 v) {
    __nv_bfloat162 p0 = __floats2bfloat162_rn(u.x, u.y);
    __nv_bfloat162 p1 = __floats2bfloat162_rn(u.z, u.w);
    __nv_bfloat162 p2 = __floats2bfloat162_rn(v.x, v.y);
    __nv_bfloat162 p3 = __floats2bfloat162_rn(v.z, v.w);
    uint4 r;
    r.x = *(unsigned*)&p0; r.y = *(unsigned*)&p1;
    r.z = *(unsigned*)&p2; r.w = *(unsigned*)&p3;
    return r;
}

__device__ __forceinline__ float blockreduce96(float s) {
    __shared__ float part[3];
#pragma unroll
    for (int off = 16; off; off >>= 1) s += __shfl_xor_sync(0xffffffffu, s, off);
    if ((threadIdx.x & 31) == 0) part[threadIdx.x >> 5] = s;
    __syncthreads();
    return part[0] + part[1] + part[2];
}

__global__ __launch_bounds__(96) void cvt_x_kernel(const float* __restrict__ in) {
    const int row = blockIdx.x;
    const int tid = threadIdx.x;
    const float4* p = (const float4*)(in + (size_t)row * D_) + 2 * tid;
    float4 u = p[0], v = p[1];
    ((uint4*)(g_xb + (size_t)row * D_))[tid] = cvt8(u, v);
    float s = u.x * u.x + u.y * u.y + u.z * u.z + u.w * u.w
            + v.x * v.x + v.y * v.y + v.z * v.z + v.w * v.w;
    s = blockreduce96(s);
    if (tid == 0) g_x2[row] = s;
}

__global__ __launch_bounds__(96) void cvt_c_kernel(const float* __restrict__ in,
                                                   const unsigned char* __restrict__ act8) {
    const int row = blockIdx.x;
    const int tid = threadIdx.x;
    const float4* p = (const float4*)(in + (size_t)row * D_) + 2 * tid;
    float4 u = p[0], v = p[1];
    ((uint4*)(g_cb + (size_t)row * D_))[tid] = cvt8(u, v);
    float s = u.x * u.x + u.y * u.y + u.z * u.z + u.w * u.w
            + v.x * v.x + v.y * v.y + v.z * v.z + v.w * v.w;
    s = blockreduce96(s);
    if (tid == 0) {
        bool int32mode = (act8[0] == 1) && (act8[1] == 0) && (act8[2] == 0) && (act8[3] == 0);
        bool a = int32mode ? (((const int*)act8)[row] != 0) : (act8[row] != 0);
        g_c2[row] = a ? s : __int_as_float(0x7f800000);
    }
}

// ---------------------------------------------------------------------------
__device__ __forceinline__ unsigned float_to_ordered(float f) {
    unsigned b = __float_as_uint(f);
    return (b & 0x80000000u) ? ~b : (b | 0x80000000u);
}

// ---------------------------------------------------------------------------
// Selection GEMM: bf16 WMMA, 4 warps of 64x64 (2x2), BK=64 (halved syncs),
// staged-bf16 LDG, register double-buffered single-stage smem, 2 CTAs/SM.
// Per-(split, col-half) winner per token; disjoint plain stores (race-free).
// ---------------------------------------------------------------------------
__global__ __launch_bounds__(128, 2) void gemm_bf16_kernel() {
    __shared__ __align__(16) __nv_bfloat16 sA[BM * SROW];
    __shared__ __align__(16) __nv_bfloat16 sB[BN * SROW];
    __shared__ __align__(16) float sbuf[4][16 * 16];

    const int tid  = threadIdx.x;
    const int lane = tid & 31;
    const int warp = tid >> 5;      // 0..3
    const int wm = warp & 1;        // 0..1 -> 64 rows each
    const int wn = warp >> 1;       // 0..1 -> 64 cols each
    const int mBase  = blockIdx.x * BM;
    const int nChunk = blockIdx.y * NCHUNK;

    const int lrow = tid >> 2;           // 0..31 (rows +0,+32,+64,+96)
    const int lseg = (tid & 3) * 16;     // elem offset 0,16,32,48 (32B per thread-slice)

    const __nv_bfloat16* Abase = g_xb + (size_t)(mBase + lrow) * D_ + lseg;

    float bestv[4];
    int   besti[4];
#pragma unroll
    for (int q = 0; q < 4; q++) { bestv[q] = __int_as_float(0x7f800000); besti[q] = nChunk; }

    for (int nt = 0; nt < NTILES; nt++) {
        const int nBase = nChunk + nt * BN;
        const __nv_bfloat16* Bbase = g_cb + (size_t)(nBase + lrow) * D_ + lseg;

        wmma::fragment<wmma::accumulator, 16, 16, 16, float> acc[4][4];
#pragma unroll
        for (int mi = 0; mi < 4; mi++)
#pragma unroll
            for (int ni = 0; ni < 4; ni++) wmma::fill_fragment(acc[mi][ni], 0.0f);

        // prologue: k-step 0 into registers (8 uint4 for A, 8 for B)
        uint4 rA[8], rB[8];
#pragma unroll
        for (int r = 0; r < 4; r++) {
            const __nv_bfloat16* ap = Abase + (size_t)(r * 32) * D_;
            const __nv_bfloat16* bp = Bbase + (size_t)(r * 32) * D_;
            rA[2 * r]     = *(const uint4*)(ap);
            rA[2 * r + 1] = *(const uint4*)(ap + 8);
            rB[2 * r]     = *(const uint4*)(bp);
            rB[2 * r + 1] = *(const uint4*)(bp + 8);
        }

        for (int kb = 0; kb < NKSTEP; kb++) {
            __syncthreads();   // previous k-step's MMAs done reading smem
#pragma unroll
            for (int r = 0; r < 4; r++) {
                *(uint4*)&sA[(lrow + r * 32) * SROW + lseg]     = rA[2 * r];
                *(uint4*)&sA[(lrow + r * 32) * SROW + lseg + 8] = rA[2 * r + 1];
                *(uint4*)&sB[(lrow + r * 32) * SROW + lseg]     = rB[2 * r];
                *(uint4*)&sB[(lrow + r * 32) * SROW + lseg + 8] = rB[2 * r + 1];
            }
            __syncthreads();
            if (kb + 1 < NKSTEP) {
                const int kg = (kb + 1) * BK;
#pragma unroll
                for (int r = 0; r < 4; r++) {
                    const __nv_bfloat16* ap = Abase + (size_t)(r * 32) * D_ + kg;
                    const __nv_bfloat16* bp = Bbase + (size_t)(r * 32) * D_ + kg;
                    rA[2 * r]     = *(const uint4*)(ap);
                    rA[2 * r + 1] = *(const uint4*)(ap + 8);
                    rB[2 * r]     = *(const uint4*)(bp);
                    rB[2 * r + 1] = *(const uint4*)(bp + 8);
                }
            }
#pragma unroll
            for (int ks = 0; ks < 4; ks++) {
                wmma::fragment<wmma::matrix_a, 16, 16, 16, __nv_bfloat16, wmma::row_major> fa[4];
#pragma unroll
                for (int mi = 0; mi < 4; mi++)
                    wmma::load_matrix_sync(fa[mi], &sA[(wm * 64 + mi * 16) * SROW + ks * 16], SROW);
#pragma unroll
                for (int ni = 0; ni < 4; ni++) {
                    // smem B is [n][k]; as a KxN matrix that's col_major with ldm=SROW
                    wmma::fragment<wmma::matrix_b, 16, 16, 16, __nv_bfloat16, wmma::col_major> fb;
                    wmma::load_matrix_sync(fb, &sB[(wn * 64 + ni * 16) * SROW + ks * 16], SROW);
#pragma unroll
                    for (int mi = 0; mi < 4; mi++)
                        wmma::mma_sync(acc[mi][ni], fa[mi], fb, acc[mi][ni]);
                }
            }
        }

        // drain frags through smem (explicit indices), update running mins
#pragma unroll
        for (int mi = 0; mi < 4; mi++) {
#pragma unroll
            for (int ni = 0; ni < 4; ni++) {
                wmma::store_matrix_sync(&sbuf[warp][0], acc[mi][ni], 16, wmma::mem_row_major);
                __syncwarp();
                const int lr = lane >> 1;
                const int cb = (lane & 1) * 8;
                const int gcol0 = nBase + wn * 64 + ni * 16 + cb;
#pragma unroll
                for (int c = 0; c < 8; c++) {
                    float dot = sbuf[warp][lr * 16 + cb + c];
                    float s = fmaf(-2.0f, dot, g_c2[gcol0 + c]);
                    if (s < bestv[mi]) { bestv[mi] = s; besti[mi] = gcol0 + c; }
                }
                __syncwarp();
            }
        }
    }

    // merge lane pairs and store this (split, half)'s winner — disjoint slots.
    const int slot = blockIdx.y * 2 + wn;
#pragma unroll
    for (int mi = 0; mi < 4; mi++) {
        unsigned long long key =
            (((unsigned long long)float_to_ordered(bestv[mi])) << 32) | (unsigned)besti[mi];
        unsigned long long o = __shfl_xor_sync(0xffffffffu, key, 1);
        if (o < key) key = o;
        if ((lane & 1) == 0) {
            int row = mBase + wm * 64 + mi * 16 + (lane >> 1);
            g_cand[(size_t)row * NCAND + slot] = key;
        }
    }
}

// ---------------------------------------------------------------------------
// Exact fp32 rescoring of the 32 nominees per token; emits final outputs.
// ---------------------------------------------------------------------------
__global__ __launch_bounds__(256) void refine_kernel(const float* __restrict__ x,
                                                     const float* __restrict__ codes,
                                                     float* __restrict__ out, int out_size) {
    const int t = blockIdx.x * 8 + (threadIdx.x >> 5);
    const int lane = threadIdx.x & 31;
    if (t >= MTOK) return;

    const float4* xr = (const float4*)(x + (size_t)t * D_);
    float4 xv[6];
#pragma unroll
    for (int j = 0; j < 6; j++) xv[j] = xr[lane + j * 32];

    unsigned long long best = 0xFFFFFFFFFFFFFFFFULL;

    for (int c = 0; c < NCAND; c++) {
        unsigned idx = (unsigned)(g_cand[(size_t)t * NCAND + c] & 0xffffffffu);
        if (idx >= NCODE) continue;             // safety guard
        const float4* cr = (const float4*)(codes + (size_t)idx * D_);
        float s = 0.f;
#pragma unroll
        for (int j = 0; j < 6; j++) {
            float4 cv = cr[lane + j * 32];
            s += xv[j].x * cv.x + xv[j].y * cv.y + xv[j].z * cv.z + xv[j].w * cv.w;
        }
#pragma unroll
        for (int off = 16; off; off >>= 1) s += __shfl_xor_sync(0xffffffffu, s, off);
        float dist = fmaf(-2.0f, s, g_c2[idx]);   // exact fp32 score; inf if inactive
        unsigned long long key =
            (((unsigned long long)float_to_ordered(dist)) << 32) | (unsigned long long)idx;
        if (key < best) best = key;
    }

    if (lane == 0) {
        unsigned u = (unsigned)(best >> 32);
        unsigned b = (u & 0x80000000u) ? (u & 0x7fffffffu) : ~u;
        float s = __uint_as_float(b);
        int idx = (int)(best & 0xffffffffu);
        float dmin = g_x2[t] + s;
        int idx_out = (dmin <= THRv) ? idx : -1;
        if (best == 0xFFFFFFFFFFFFFFFFULL) { idx_out = -1; dmin = __int_as_float(0x7f800000); }
        out[t] = (float)idx_out;
        if (out_size >= 2 * MTOK) out[MTOK + t] = dmin;
    }
}

// ---------------------------------------------------------------------------
extern "C" void kernel_launch(void* const* d_in, const int* in_sizes, int n_in,
                              void* d_out, int out_size) {
    const float* x     = (const float*)d_in[0];
    const float* codes = (const float*)d_in[1];
    const unsigned char* act = (const unsigned char*)d_in[2];

    cvt_x_kernel<<<MTOK, 96>>>(x);
    cvt_c_kernel<<<NCODE, 96>>>(codes, act);
    gemm_bf16_kernel<<<dim3(MTOK / BM, NSPLIT), 128>>>();
    refine_kernel<<<MTOK / 8, 256>>>(x, codes, (float*)d_out, out_size);
}